// round 14
// baseline (speedup 1.0000x reference)
#include <cuda_runtime.h>
#include <cuda_fp16.h>
#include <math.h>
#include <stdint.h>

// ---------------- problem constants ----------------
#define BB   32
#define TT   512
#define DENC 512
#define HH   640
#define VV   4096
#define MM   (BB*TT)        // 16384
#define H4   (4*HH)         // 2560
#define OUT0 ((size_t)MM*VV) // 67108864
#define K1   DENC           // 512
#define K2   HH             // 640

// ---------------- PTX helpers ----------------
__device__ __forceinline__ uint32_t smem_u32(const void* p) {
    uint32_t a;
    asm("{ .reg .u64 t; cvta.to.shared.u64 t, %1; cvt.u32.u64 %0, t; }" : "=r"(a) : "l"(p));
    return a;
}
#define CP_ASYNC16(sa, ga) \
    asm volatile("cp.async.cg.shared.global [%0], [%1], 16;" :: "r"(sa), "l"(ga))
#define CP_COMMIT() asm volatile("cp.async.commit_group;")
#define CP_WAIT1()  asm volatile("cp.async.wait_group 1;" ::: "memory")
#define CP_WAIT0()  asm volatile("cp.async.wait_group 0;" ::: "memory")
#define LDSM4(r0, r1, r2, r3, addr) \
    asm volatile("ldmatrix.sync.aligned.m8n8.x4.shared.b16 {%0,%1,%2,%3}, [%4];" \
        : "=r"(r0), "=r"(r1), "=r"(r2), "=r"(r3) : "r"(addr))

__device__ __forceinline__ void mma16816(float* c, const uint32_t* a, const uint32_t* b) {
    asm volatile(
        "mma.sync.aligned.m16n8k16.row.col.f32.f16.f16.f32 "
        "{%0,%1,%2,%3},{%4,%5,%6,%7},{%8,%9},{%0,%1,%2,%3};"
        : "+f"(c[0]), "+f"(c[1]), "+f"(c[2]), "+f"(c[3])
        : "r"(a[0]), "r"(a[1]), "r"(a[2]), "r"(a[3]), "r"(b[0]), "r"(b[1]));
}

// ---------------- scratch (device globals; no allocation) ----------------
__device__ __align__(16) float g_x[BB*HH];
__device__ __align__(16) float g_h0[BB*HH];
__device__ __align__(16) float g_c0[BB*HH];
__device__ __align__(16) float g_h1[BB*HH];
__device__ __align__(16) float g_c1[BB*HH];
__device__ __align__(16) float g_g[BB*HH];
// fp16 single-plane operands
__device__ __align__(16) __half g_A1[(size_t)MM*K1];  // 16.8 MB
__device__ __align__(16) __half g_B1[(size_t)HH*K1];
__device__ __align__(16) __half g_A2[(size_t)MM*K2];  // 21 MB
__device__ __align__(16) __half g_B2[(size_t)VV*K2];  // 5.2 MB

// ---------------- embed (with inline int64/int32 sniff) ----------------
__global__ void k_embed(const int* __restrict__ t, const float* __restrict__ embed)
{
    int i = blockIdx.x*blockDim.x + threadIdx.x;
    if (i >= BB*HH) return;
    bool is64 = true;
    #pragma unroll
    for (int w = 1; w < 32; w += 2)
        if (t[w] != 0) { is64 = false; break; }
    int b = i / HH, k = i % HH;
    int tok = is64 ? t[2*b] : t[b];
    if (tok < 0) tok = 0;
    if (tok >= VV) tok = VV - 1;
    g_x[i] = embed[(size_t)tok*HH + k];
}

// ---------------- decoder LSTM cell: one block per output column j ----------------
// Warp gt (0..3) computes gate gt for all 32 batch rows:
//   gate[m] = sum_k Wih[gt*H+j][k]*X[m][k] + Whh[gt*H+j][k]*Hp[m][k]
// Lane l owns k = 32*c + l. Fused pointwise in warp 0. No partial buffers.
__global__ __launch_bounds__(128) void k_cell2(
    const float* __restrict__ X,  const float* __restrict__ Hp,
    const float* __restrict__ Cp,
    const float* __restrict__ Wih, const float* __restrict__ Whh,
    const float* __restrict__ bih, const float* __restrict__ bhh,
    float* __restrict__ Hn, float* __restrict__ Cn)
{
    __shared__ float red[4][32][33];
    __shared__ float gs[4][32];
    const int j   = blockIdx.x;          // 0..639
    const int gt  = threadIdx.x >> 5;    // gate
    const int l   = threadIdx.x & 31;

    const float* w1 = Wih + (size_t)(gt*HH + j)*HH;
    const float* w2 = Whh + (size_t)(gt*HH + j)*HH;

    float acc[32];
    #pragma unroll
    for (int m = 0; m < 32; m++) acc[m] = 0.f;

    #pragma unroll 4
    for (int c = 0; c < HH/32; c++) {
        const int k = c*32 + l;
        const float a = w1[k];
        const float b = w2[k];
        #pragma unroll
        for (int m = 0; m < 32; m++)
            acc[m] += a * X[m*HH + k] + b * Hp[m*HH + k];
    }
    // transpose-reduce within the warp's smem quadrant
    #pragma unroll
    for (int m = 0; m < 32; m++) red[gt][l][m] = acc[m];
    __syncwarp();
    float s = 0.f;
    #pragma unroll
    for (int t = 0; t < 32; t++) s += red[gt][t][l];   // lane l -> batch row l
    s += bih[gt*HH + j] + bhh[gt*HH + j];
    gs[gt][l] = s;
    __syncthreads();
    if (gt == 0) {
        float gi = gs[0][l], gf = gs[1][l], gg = gs[2][l], go = gs[3][l];
        float i_ = 1.f / (1.f + expf(-gi));
        float f_ = 1.f / (1.f + expf(-gf));
        float g_ = tanhf(gg);
        float o_ = 1.f / (1.f + expf(-go));
        float cn = f_ * Cp[(size_t)l*HH + j] + i_ * g_;
        Cn[(size_t)l*HH + j] = cn;
        Hn[(size_t)l*HH + j] = o_ * tanhf(cn);
    }
}

// ---------------- pred projection: 4 columns per block (one per warp) ----------------
__global__ __launch_bounds__(128) void k_pred2(
    const float* __restrict__ A, const float* __restrict__ W,
    const float* __restrict__ bias, float* __restrict__ C)
{
    __shared__ float red[4][32][33];
    const int wid = threadIdx.x >> 5;
    const int l   = threadIdx.x & 31;
    const int j   = blockIdx.x*4 + wid;   // 0..639

    const float* wr = W + (size_t)j*HH;
    float acc[32];
    #pragma unroll
    for (int m = 0; m < 32; m++) acc[m] = 0.f;
    #pragma unroll 4
    for (int c = 0; c < HH/32; c++) {
        const int k = c*32 + l;
        const float w = wr[k];
        #pragma unroll
        for (int m = 0; m < 32; m++)
            acc[m] += w * A[m*HH + k];
    }
    #pragma unroll
    for (int m = 0; m < 32; m++) red[wid][l][m] = acc[m];
    __syncwarp();
    float s = 0.f;
    #pragma unroll
    for (int t = 0; t < 32; t++) s += red[wid][t][l];
    C[(size_t)l*HH + j] = s + bias[j];
}

// ---------------- fused staging: encT + both weight fp16 conversions ----------------
#define NB_ENC  8192                      // (DENC/32)*(TT/32)*BB
#define NB_WENC 320                       // HH*DENC/1024
#define NB_WOUT 2560                      // VV*HH/1024
__global__ __launch_bounds__(256) void k_stage(
    const float* __restrict__ enc, const float* __restrict__ wenc,
    const float* __restrict__ wout)
{
    __shared__ float tile[32][33];
    const int b = blockIdx.x;
    const int tid = threadIdx.x;
    if (b < NB_ENC) {
        int bb = b >> 8;
        int rb = b & 255;
        int d0 = (rb >> 4) * 32;
        int t0 = (rb & 15) * 32;
        int tx = tid & 31, ty = tid >> 5;    // (32, 8)
        const float* src = enc + ((size_t)bb*DENC + d0)*TT + t0;
        #pragma unroll
        for (int j = 0; j < 4; j++)
            tile[ty + 8*j][tx] = src[(size_t)(ty + 8*j)*TT + tx];
        __syncthreads();
        #pragma unroll
        for (int j = 0; j < 4; j++) {
            int tl = ty + 8*j;
            size_t m = (size_t)bb*TT + t0 + tl;
            g_A1[m*K1 + d0 + tx] = __float2half_rn(tile[tx][tl]);
        }
    } else if (b < NB_ENC + NB_WENC) {
        size_t i = (size_t)(b - NB_ENC)*1024 + tid*4;
        float4 v = *(const float4*)&wenc[i];
        __half2 p0 = __floats2half2_rn(v.x, v.y);
        __half2 p1 = __floats2half2_rn(v.z, v.w);
        *(uint2*)&g_B1[i] = make_uint2(*(uint32_t*)&p0, *(uint32_t*)&p1);
    } else {
        size_t i = (size_t)(b - NB_ENC - NB_WENC)*1024 + tid*4;
        float4 v = *(const float4*)&wout[i];
        __half2 p0 = __floats2half2_rn(v.x, v.y);
        __half2 p1 = __floats2half2_rn(v.z, v.w);
        *(uint2*)&g_B2[i] = make_uint2(*(uint32_t*)&p0, *(uint32_t*)&p1);
    }
}

// ---------------- HMMA GEMM, single fp16 plane, 3-stage pipeline (R12-proven) ----------------
// MODE 0: epilogue relu(acc + bias + gvec[b]) -> g_A2 fp16
// MODE 1: epilogue acc + bias -> outf fp32
#define ROWB   80          // 64B data + 16B pad
#define TILEB  (128*ROWB)  // 10240 per plane
#define STAGEB (2*TILEB)   // 20480 per stage (A + B)
#define NSTG   3
#define SMEM_HM (NSTG*STAGEB) // 61440

template<int KP, int MODE>
__global__ __launch_bounds__(256, 2) void k_hmma(
    const __half* __restrict__ A, const __half* __restrict__ B,
    const float* __restrict__ bias, const float* __restrict__ gvec,
    float* __restrict__ outf)
{
    extern __shared__ __align__(16) char sb[];
    const uint32_t sbase = smem_u32(sb);

    const int tid = threadIdx.x;
    const int wid = tid >> 5;
    const int lid = tid & 31;

    // tile-raster swizzle: 8 m-tiles per n sweep (guarded bijection)
    int m0, n0;
    if ((gridDim.y & 7) == 0) {
        int bid = blockIdx.y * gridDim.x + blockIdx.x;
        int grp = bid / (gridDim.x * 8);
        int rem = bid % (gridDim.x * 8);
        m0 = (grp*8 + (rem & 7)) * 128;
        n0 = (rem >> 3) * 128;
    } else {
        m0 = blockIdx.y * 128;
        n0 = blockIdx.x * 128;
    }

    const int wm = (wid & 3) * 32;
    const int wn = (wid >> 2) * 64;

    const int q   = lid >> 3;
    const int lr8 = lid & 7;
    uint32_t offA[2], offB[4];
    #pragma unroll
    for (int mi = 0; mi < 2; mi++)
        offA[mi] = (uint32_t)((wm + mi*16 + (q&1)*8 + lr8)*ROWB + (q>>1)*16);
    #pragma unroll
    for (int n2 = 0; n2 < 4; n2++)
        offB[n2] = (uint32_t)(TILEB + (wn + n2*16 + (q>>1)*8 + lr8)*ROWB + (q&1)*16);

    float acc[2][8][4];
    #pragma unroll
    for (int mi = 0; mi < 2; mi++)
        #pragma unroll
        for (int ni = 0; ni < 8; ni++)
            #pragma unroll
            for (int v = 0; v < 4; v++) acc[mi][ni][v] = 0.f;

    const int r_ld = tid >> 2;
    const int c_ld = tid & 3;
    const int nch = KP / 32;

    auto load_stage = [&](int k0, int st) {
        uint32_t sa = sbase + st*STAGEB + r_ld*ROWB + c_ld*16;
        const __half* gA = A + (size_t)(m0 + r_ld)*KP + k0 + c_ld*8;
        const __half* gB = B + (size_t)(n0 + r_ld)*KP + k0 + c_ld*8;
        CP_ASYNC16(sa,          gA);
        CP_ASYNC16(sa + TILEB,  gB);
        const size_t half_off = (size_t)64*KP;
        CP_ASYNC16(sa + 64*ROWB,         gA + half_off);
        CP_ASYNC16(sa + TILEB + 64*ROWB, gB + half_off);
        CP_COMMIT();
    };

    // prologue: stages 0 and 1 in flight
    load_stage(0, 0);
    if (nch > 1) load_stage(32, 1);

    for (int ch = 0; ch < nch; ch++) {
        if (ch + 1 < nch) { CP_WAIT1(); } else { CP_WAIT0(); }
        __syncthreads();   // stage ch visible; all warps done with stage (ch-1)

        if (ch + 2 < nch) load_stage((ch + 2)*32, (ch + 2) % NSTG);

        const uint32_t pS = sbase + (ch % NSTG)*STAGEB;
        #pragma unroll
        for (int ks = 0; ks < 2; ks++) {
            const uint32_t kb = ks * 32;
            uint32_t af[2][4], bf[8][2];
            #pragma unroll
            for (int mi = 0; mi < 2; mi++)
                LDSM4(af[mi][0], af[mi][1], af[mi][2], af[mi][3], pS + offA[mi] + kb);
            #pragma unroll
            for (int n2 = 0; n2 < 4; n2++)
                LDSM4(bf[2*n2][0], bf[2*n2][1], bf[2*n2+1][0], bf[2*n2+1][1],
                      pS + offB[n2] + kb);
            #pragma unroll
            for (int mi = 0; mi < 2; mi++)
                #pragma unroll
                for (int ni = 0; ni < 8; ni++)
                    mma16816(acc[mi][ni], af[mi], bf[ni]);
        }
    }
    __syncthreads();

    // ---------------- epilogue ----------------
    const int lrow  = lid >> 2;
    const int lcol2 = (lid & 3) * 2;
    if (MODE == 1) {
        #pragma unroll
        for (int mi = 0; mi < 2; mi++) {
            const int gr = m0 + wm + mi*16 + lrow;
            #pragma unroll
            for (int ni = 0; ni < 8; ni++) {
                const int gc = n0 + wn + ni*8 + lcol2;
                const float b0 = bias[gc], b1 = bias[gc+1];
                float2 v0 = {acc[mi][ni][0] + b0, acc[mi][ni][1] + b1};
                float2 v1 = {acc[mi][ni][2] + b0, acc[mi][ni][3] + b1};
                *(float2*)&outf[(size_t)gr*VV + gc]     = v0;
                *(float2*)&outf[(size_t)(gr+8)*VV + gc] = v1;
            }
        }
    } else {
        const int b = m0 >> 9;
        const float* gv = gvec + b*HH;
        unsigned short* oh = (unsigned short*)g_A2;
        #pragma unroll
        for (int mi = 0; mi < 2; mi++) {
            const int gr = m0 + wm + mi*16 + lrow;
            #pragma unroll
            for (int ni = 0; ni < 8; ni++) {
                const int gc = n0 + wn + ni*8 + lcol2;   // even
                const float add0 = bias[gc]   + gv[gc];
                const float add1 = bias[gc+1] + gv[gc+1];
                #pragma unroll
                for (int half = 0; half < 2; half++) {
                    const int r = gr + half*8;
                    float v0 = fmaxf(acc[mi][ni][2*half+0] + add0, 0.f);
                    float v1 = fmaxf(acc[mi][ni][2*half+1] + add1, 0.f);
                    __half h0 = __float2half_rn(v0);
                    __half h1 = __float2half_rn(v1);
                    uint32_t pk = (uint32_t)*(unsigned short*)&h0
                                | ((uint32_t)*(unsigned short*)&h1 << 16);
                    *(uint32_t*)&oh[(size_t)r*K2 + gc] = pk;
                }
            }
        }
    }
}

// ---------------- tail ----------------
__global__ void k_tail(const int* __restrict__ tlen, float* __restrict__ out,
                       size_t out_cap)
{
    size_t i = blockIdx.x*blockDim.x + threadIdx.x;
    size_t idx = OUT0 + i;
    if (idx >= out_cap) return;
    if (i < 32) { out[idx] = (float)tlen[i]; return; }
    size_t j = i - 32;
    const size_t S = BB*HH;
    if (j < S)            out[idx] = g_h0[j];
    else if (j < 2*S)     out[idx] = g_h1[j - S];
    else if (j < 3*S)     out[idx] = g_c0[j - 2*S];
    else if (j < 4*S)     out[idx] = g_c1[j - 3*S];
}

// ---------------- launch ----------------
extern "C" void kernel_launch(void* const* d_in, const int* in_sizes, int n_in,
                              void* d_out, int out_size)
{
    const float*      enc    = (const float*)d_in[0];
    const int*        tgt32  = (const int*)d_in[1];
    const int*        tlen   = (const int*)d_in[2];
    const float*      is1    = (const float*)d_in[3];
    const float*      is2    = (const float*)d_in[4];
    const float*      wih0   = (const float*)d_in[5];
    const float*      whh0   = (const float*)d_in[6];
    const float*      bih0   = (const float*)d_in[7];
    const float*      bhh0   = (const float*)d_in[8];
    const float*      wih1   = (const float*)d_in[9];
    const float*      whh1   = (const float*)d_in[10];
    const float*      bih1   = (const float*)d_in[11];
    const float*      bhh1   = (const float*)d_in[12];
    const float*      embed  = (const float*)d_in[13];
    const float*      wenc   = (const float*)d_in[14];
    const float*      benc   = (const float*)d_in[15];
    const float*      wpred  = (const float*)d_in[16];
    const float*      bpred  = (const float*)d_in[17];
    const float*      wout   = (const float*)d_in[18];
    const float*      bout   = (const float*)d_in[19];
    float*            out    = (float*)d_out;

    float *x, *h0, *c0, *h1, *c1, *gj;
    cudaGetSymbolAddress((void**)&x,  g_x);
    cudaGetSymbolAddress((void**)&h0, g_h0);
    cudaGetSymbolAddress((void**)&c0, g_c0);
    cudaGetSymbolAddress((void**)&h1, g_h1);
    cudaGetSymbolAddress((void**)&c1, g_c1);
    cudaGetSymbolAddress((void**)&gj, g_g);

    __half *a1, *b1, *a2, *b2;
    cudaGetSymbolAddress((void**)&a1, g_A1);
    cudaGetSymbolAddress((void**)&b1, g_B1);
    cudaGetSymbolAddress((void**)&a2, g_A2);
    cudaGetSymbolAddress((void**)&b2, g_B2);

    cudaFuncSetAttribute(k_hmma<K1, 0>, cudaFuncAttributeMaxDynamicSharedMemorySize, SMEM_HM);
    cudaFuncSetAttribute(k_hmma<K2, 1>, cudaFuncAttributeMaxDynamicSharedMemorySize, SMEM_HM);

    // decoder (column-per-block cells, fused pointwise)
    k_embed<<<(BB*HH + 255)/256, 256>>>(tgt32, embed);
    k_cell2<<<HH, 128>>>(x,  is1,          is2,          wih0, whh0, bih0, bhh0, h0, c0);
    k_cell2<<<HH, 128>>>(h0, is1 + BB*HH,  is2 + BB*HH,  wih1, whh1, bih1, bhh1, h1, c1);
    k_pred2<<<HH/4, 128>>>(h1, wpred, bpred, gj);

    // staging (encT + weight conversions, one kernel)
    k_stage<<<NB_ENC + NB_WENC + NB_WOUT, 256>>>(enc, wenc, wout);

    // joint network (mma.sync fp16, 3-stage pipeline)
    k_hmma<K1, 0><<<dim3(HH/128, MM/128), 256, SMEM_HM>>>(a1, b1, benc, gj, nullptr);
    k_hmma<K2, 1><<<dim3(VV/128, MM/128), 256, SMEM_HM>>>(a2, b2, bout, nullptr, out);

    // extra tuple outputs
    size_t cap = (size_t)out_size;
    if (cap > OUT0) {
        size_t tail_n = cap - OUT0;
        k_tail<<<(int)((tail_n + 255)/256), 256>>>(tlen, out, cap);
    }
}

// round 15
// speedup vs baseline: 1.6572x; 1.6572x over previous
#include <cuda_runtime.h>
#include <cuda_fp16.h>
#include <math.h>
#include <stdint.h>

// ---------------- problem constants ----------------
#define BB   32
#define TT   512
#define DENC 512
#define HH   640
#define VV   4096
#define MM   (BB*TT)        // 16384
#define H4   (4*HH)         // 2560
#define OUT0 ((size_t)MM*VV) // 67108864
#define K1   DENC           // 512
#define K2   HH             // 640
#define SPL  4              // decoder K-splits (640/4 = 160)

// ---------------- PTX helpers ----------------
__device__ __forceinline__ uint32_t smem_u32(const void* p) {
    uint32_t a;
    asm("{ .reg .u64 t; cvta.to.shared.u64 t, %1; cvt.u32.u64 %0, t; }" : "=r"(a) : "l"(p));
    return a;
}
#define CP_ASYNC16(sa, ga) \
    asm volatile("cp.async.cg.shared.global [%0], [%1], 16;" :: "r"(sa), "l"(ga))
#define CP_COMMIT() asm volatile("cp.async.commit_group;")
#define CP_WAIT1()  asm volatile("cp.async.wait_group 1;" ::: "memory")
#define CP_WAIT0()  asm volatile("cp.async.wait_group 0;" ::: "memory")
#define LDSM4(r0, r1, r2, r3, addr) \
    asm volatile("ldmatrix.sync.aligned.m8n8.x4.shared.b16 {%0,%1,%2,%3}, [%4];" \
        : "=r"(r0), "=r"(r1), "=r"(r2), "=r"(r3) : "r"(addr))

__device__ __forceinline__ void mma16816(float* c, const uint32_t* a, const uint32_t* b) {
    asm volatile(
        "mma.sync.aligned.m16n8k16.row.col.f32.f16.f16.f32 "
        "{%0,%1,%2,%3},{%4,%5,%6,%7},{%8,%9},{%0,%1,%2,%3};"
        : "+f"(c[0]), "+f"(c[1]), "+f"(c[2]), "+f"(c[3])
        : "r"(a[0]), "r"(a[1]), "r"(a[2]), "r"(a[3]), "r"(b[0]), "r"(b[1]));
}

// ---------------- scratch (device globals; no allocation) ----------------
__device__ __align__(16) float g_x[BB*HH];
__device__ __align__(16) float g_h0[BB*HH];
__device__ __align__(16) float g_c0[BB*HH];
__device__ __align__(16) float g_h1[BB*HH];
__device__ __align__(16) float g_c1[BB*HH];
__device__ __align__(16) float g_g[BB*HH];
__device__ __align__(16) float g_part[SPL*BB*H4];   // decoder partials
// fp16 single-plane operands
__device__ __align__(16) __half g_A1[(size_t)MM*K1];  // 16.8 MB
__device__ __align__(16) __half g_B1[(size_t)HH*K1];
__device__ __align__(16) __half g_A2[(size_t)MM*K2];  // 21 MB
__device__ __align__(16) __half g_B2[(size_t)VV*K2];  // 5.2 MB

// ---------------- embed (with inline int64/int32 sniff) ----------------
__global__ void k_embed(const int* __restrict__ t, const float* __restrict__ embed)
{
    int i = blockIdx.x*blockDim.x + threadIdx.x;
    if (i >= BB*HH) return;
    bool is64 = true;
    #pragma unroll
    for (int w = 1; w < 32; w += 2)
        if (t[w] != 0) { is64 = false; break; }
    int b = i / HH, k = i % HH;
    int tok = is64 ? t[2*b] : t[b];
    if (tok < 0) tok = 0;
    if (tok >= VV) tok = VV - 1;
    g_x[i] = embed[(size_t)tok*HH + k];
}

// ---------------- decoder partial GEMM, pipelined (K-split) ----------------
// part[s][32][N] = A[:, slice_s] @ W[:, slice_s]^T (+ A2 @ W2^T)
// W double-buffered via cp.async (broadcast reads -> no pad needed);
// A register-prefetched into padded smem (conflict-free column reads).
__global__ __launch_bounds__(256) void k_part2(
    const float* __restrict__ A,  const float* __restrict__ A2,
    const float* __restrict__ W,  const float* __restrict__ W2,
    float* __restrict__ part, int N, int K)
{
    __shared__ float As [32][33];
    __shared__ float A2s[32][33];
    __shared__ __align__(16) float Ws[2][2][32][32];   // [stage][mat][n][k]
    const int tid = threadIdx.x;
    const int n0  = blockIdx.x * 32;
    const int s   = blockIdx.y;
    const int KS  = K / SPL;
    const int kb  = s * KS;
    const int m   = tid & 31;
    const int nid = tid >> 5;
    const int lrow = tid >> 3;         // 0..31
    const int lcol = (tid & 7) * 4;    // 0..28
    const bool dual = (A2 != nullptr);
    const uint32_t wsbase = smem_u32(Ws);

    const int wrow = tid >> 3;  // 0..31
    const int wseg = tid & 7;   // 0..7 (16B segments)

    auto loadW = [&](int k0, int st) {
        uint32_t sa = wsbase + (uint32_t)((((st*2 + 0)*32 + wrow)*32 + wseg*4)*4);
        CP_ASYNC16(sa, W + (size_t)(n0 + wrow)*K + k0 + wseg*4);
        if (dual) {
            uint32_t sa2 = wsbase + (uint32_t)((((st*2 + 1)*32 + wrow)*32 + wseg*4)*4);
            CP_ASYNC16(sa2, W2 + (size_t)(n0 + wrow)*K + k0 + wseg*4);
        }
        CP_COMMIT();
    };

    float4 rA = {0,0,0,0}, rA2 = {0,0,0,0};
    auto loadAreg = [&](int k0) {
        rA = *(const float4*)(A + (size_t)lrow*K + k0 + lcol);
        if (dual) rA2 = *(const float4*)(A2 + (size_t)lrow*K + k0 + lcol);
    };

    float acc[4] = {0.f, 0.f, 0.f, 0.f};
    const int nch = KS / 32;

    loadAreg(kb);
    loadW(kb, 0);

    for (int ch = 0; ch < nch; ch++) {
        const int st = ch & 1;
        // publish A chunk ch (regs -> padded smem)
        As[lrow][lcol+0] = rA.x;  As[lrow][lcol+1] = rA.y;
        As[lrow][lcol+2] = rA.z;  As[lrow][lcol+3] = rA.w;
        if (dual) {
            A2s[lrow][lcol+0] = rA2.x; A2s[lrow][lcol+1] = rA2.y;
            A2s[lrow][lcol+2] = rA2.z; A2s[lrow][lcol+3] = rA2.w;
        }
        CP_WAIT0();          // W chunk ch landed (only group outstanding)
        __syncthreads();

        if (ch + 1 < nch) {  // prefetch chunk ch+1 (overlaps compute)
            loadAreg(kb + (ch + 1)*32);
            loadW(kb + (ch + 1)*32, st ^ 1);
        }

        if (dual) {
            #pragma unroll 8
            for (int kk = 0; kk < 32; kk++) {
                float av = As[m][kk], a2v = A2s[m][kk];
                #pragma unroll
                for (int j = 0; j < 4; j++) {
                    int nl = nid + 8*j;
                    acc[j] += av * Ws[st][0][nl][kk] + a2v * Ws[st][1][nl][kk];
                }
            }
        } else {
            #pragma unroll 8
            for (int kk = 0; kk < 32; kk++) {
                float av = As[m][kk];
                #pragma unroll
                for (int j = 0; j < 4; j++)
                    acc[j] += av * Ws[st][0][nid + 8*j][kk];
            }
        }
        __syncthreads();     // protect As before next overwrite
    }
    #pragma unroll
    for (int j = 0; j < 4; j++)
        part[((size_t)s*32 + m)*N + n0 + nid + 8*j] = acc[j];
}

// ---------------- decoder reduce + LSTM activation ----------------
__global__ void k_redcell(const float* __restrict__ part,
                          const float* __restrict__ Cp,
                          const float* __restrict__ bih, const float* __restrict__ bhh,
                          float* __restrict__ Hn, float* __restrict__ Cn)
{
    int i = blockIdx.x*blockDim.x + threadIdx.x;
    if (i >= BB*HH) return;
    int m = i / HH, j = i % HH;
    float gi = 0.f, gf = 0.f, gg = 0.f, go = 0.f;
    #pragma unroll
    for (int s = 0; s < SPL; s++) {
        const float* p = part + ((size_t)s*32 + m)*H4;
        gi += p[j]; gf += p[HH + j]; gg += p[2*HH + j]; go += p[3*HH + j];
    }
    gi += bih[j]        + bhh[j];
    gf += bih[HH + j]   + bhh[HH + j];
    gg += bih[2*HH + j] + bhh[2*HH + j];
    go += bih[3*HH + j] + bhh[3*HH + j];
    float i_ = 1.f / (1.f + expf(-gi));
    float f_ = 1.f / (1.f + expf(-gf));
    float g_ = tanhf(gg);
    float o_ = 1.f / (1.f + expf(-go));
    float cn = f_ * Cp[i] + i_ * g_;
    Cn[i] = cn;
    Hn[i] = o_ * tanhf(cn);
}

__global__ void k_redpred(const float* __restrict__ part,
                          const float* __restrict__ bias, float* __restrict__ C)
{
    int i = blockIdx.x*blockDim.x + threadIdx.x;
    if (i >= BB*HH) return;
    int m = i / HH, n = i % HH;
    float a = 0.f;
    #pragma unroll
    for (int s = 0; s < SPL; s++)
        a += part[((size_t)s*32 + m)*HH + n];
    C[i] = a + bias[n];
}

// ---------------- fused staging: encT + both weight fp16 conversions ----------------
#define NB_ENC  8192                      // (DENC/32)*(TT/32)*BB
#define NB_WENC 320                       // HH*DENC/1024
#define NB_WOUT 2560                      // VV*HH/1024
__global__ __launch_bounds__(256) void k_stage(
    const float* __restrict__ enc, const float* __restrict__ wenc,
    const float* __restrict__ wout)
{
    __shared__ float tile[32][33];
    const int b = blockIdx.x;
    const int tid = threadIdx.x;
    if (b < NB_ENC) {
        int bb = b >> 8;
        int rb = b & 255;
        int d0 = (rb >> 4) * 32;
        int t0 = (rb & 15) * 32;
        int tx = tid & 31, ty = tid >> 5;    // (32, 8)
        const float* src = enc + ((size_t)bb*DENC + d0)*TT + t0;
        #pragma unroll
        for (int j = 0; j < 4; j++)
            tile[ty + 8*j][tx] = src[(size_t)(ty + 8*j)*TT + tx];
        __syncthreads();
        #pragma unroll
        for (int j = 0; j < 4; j++) {
            int tl = ty + 8*j;
            size_t m = (size_t)bb*TT + t0 + tl;
            g_A1[m*K1 + d0 + tx] = __float2half_rn(tile[tx][tl]);
        }
    } else if (b < NB_ENC + NB_WENC) {
        size_t i = (size_t)(b - NB_ENC)*1024 + tid*4;
        float4 v = *(const float4*)&wenc[i];
        __half2 p0 = __floats2half2_rn(v.x, v.y);
        __half2 p1 = __floats2half2_rn(v.z, v.w);
        *(uint2*)&g_B1[i] = make_uint2(*(uint32_t*)&p0, *(uint32_t*)&p1);
    } else {
        size_t i = (size_t)(b - NB_ENC - NB_WENC)*1024 + tid*4;
        float4 v = *(const float4*)&wout[i];
        __half2 p0 = __floats2half2_rn(v.x, v.y);
        __half2 p1 = __floats2half2_rn(v.z, v.w);
        *(uint2*)&g_B2[i] = make_uint2(*(uint32_t*)&p0, *(uint32_t*)&p1);
    }
}

// ---------------- HMMA GEMM, single fp16 plane, 3-stage pipeline (R12-proven) ----------------
// MODE 0: epilogue relu(acc + bias + gvec[b]) -> g_A2 fp16
// MODE 1: epilogue acc + bias -> outf fp32
#define ROWB   80          // 64B data + 16B pad
#define TILEB  (128*ROWB)  // 10240 per plane
#define STAGEB (2*TILEB)   // 20480 per stage (A + B)
#define NSTG   3
#define SMEM_HM (NSTG*STAGEB) // 61440

template<int KP, int MODE>
__global__ __launch_bounds__(256, 2) void k_hmma(
    const __half* __restrict__ A, const __half* __restrict__ B,
    const float* __restrict__ bias, const float* __restrict__ gvec,
    float* __restrict__ outf)
{
    extern __shared__ __align__(16) char sb[];
    const uint32_t sbase = smem_u32(sb);

    const int tid = threadIdx.x;
    const int wid = tid >> 5;
    const int lid = tid & 31;

    // tile-raster swizzle: 8 m-tiles per n sweep (guarded bijection)
    int m0, n0;
    if ((gridDim.y & 7) == 0) {
        int bid = blockIdx.y * gridDim.x + blockIdx.x;
        int grp = bid / (gridDim.x * 8);
        int rem = bid % (gridDim.x * 8);
        m0 = (grp*8 + (rem & 7)) * 128;
        n0 = (rem >> 3) * 128;
    } else {
        m0 = blockIdx.y * 128;
        n0 = blockIdx.x * 128;
    }

    const int wm = (wid & 3) * 32;
    const int wn = (wid >> 2) * 64;

    const int q   = lid >> 3;
    const int lr8 = lid & 7;
    uint32_t offA[2], offB[4];
    #pragma unroll
    for (int mi = 0; mi < 2; mi++)
        offA[mi] = (uint32_t)((wm + mi*16 + (q&1)*8 + lr8)*ROWB + (q>>1)*16);
    #pragma unroll
    for (int n2 = 0; n2 < 4; n2++)
        offB[n2] = (uint32_t)(TILEB + (wn + n2*16 + (q>>1)*8 + lr8)*ROWB + (q&1)*16);

    float acc[2][8][4];
    #pragma unroll
    for (int mi = 0; mi < 2; mi++)
        #pragma unroll
        for (int ni = 0; ni < 8; ni++)
            #pragma unroll
            for (int v = 0; v < 4; v++) acc[mi][ni][v] = 0.f;

    const int r_ld = tid >> 2;
    const int c_ld = tid & 3;
    const int nch = KP / 32;

    auto load_stage = [&](int k0, int st) {
        uint32_t sa = sbase + st*STAGEB + r_ld*ROWB + c_ld*16;
        const __half* gA = A + (size_t)(m0 + r_ld)*KP + k0 + c_ld*8;
        const __half* gB = B + (size_t)(n0 + r_ld)*KP + k0 + c_ld*8;
        CP_ASYNC16(sa,          gA);
        CP_ASYNC16(sa + TILEB,  gB);
        const size_t half_off = (size_t)64*KP;
        CP_ASYNC16(sa + 64*ROWB,         gA + half_off);
        CP_ASYNC16(sa + TILEB + 64*ROWB, gB + half_off);
        CP_COMMIT();
    };

    // prologue: stages 0 and 1 in flight
    load_stage(0, 0);
    if (nch > 1) load_stage(32, 1);

    for (int ch = 0; ch < nch; ch++) {
        if (ch + 1 < nch) { CP_WAIT1(); } else { CP_WAIT0(); }
        __syncthreads();   // stage ch visible; all warps done with stage (ch-1)

        if (ch + 2 < nch) load_stage((ch + 2)*32, (ch + 2) % NSTG);

        const uint32_t pS = sbase + (ch % NSTG)*STAGEB;
        #pragma unroll
        for (int ks = 0; ks < 2; ks++) {
            const uint32_t kb = ks * 32;
            uint32_t af[2][4], bf[8][2];
            #pragma unroll
            for (int mi = 0; mi < 2; mi++)
                LDSM4(af[mi][0], af[mi][1], af[mi][2], af[mi][3], pS + offA[mi] + kb);
            #pragma unroll
            for (int n2 = 0; n2 < 4; n2++)
                LDSM4(bf[2*n2][0], bf[2*n2][1], bf[2*n2+1][0], bf[2*n2+1][1],
                      pS + offB[n2] + kb);
            #pragma unroll
            for (int mi = 0; mi < 2; mi++)
                #pragma unroll
                for (int ni = 0; ni < 8; ni++)
                    mma16816(acc[mi][ni], af[mi], bf[ni]);
        }
    }
    __syncthreads();

    // ---------------- epilogue ----------------
    const int lrow  = lid >> 2;
    const int lcol2 = (lid & 3) * 2;
    if (MODE == 1) {
        #pragma unroll
        for (int mi = 0; mi < 2; mi++) {
            const int gr = m0 + wm + mi*16 + lrow;
            #pragma unroll
            for (int ni = 0; ni < 8; ni++) {
                const int gc = n0 + wn + ni*8 + lcol2;
                const float b0 = bias[gc], b1 = bias[gc+1];
                float2 v0 = {acc[mi][ni][0] + b0, acc[mi][ni][1] + b1};
                float2 v1 = {acc[mi][ni][2] + b0, acc[mi][ni][3] + b1};
                *(float2*)&outf[(size_t)gr*VV + gc]     = v0;
                *(float2*)&outf[(size_t)(gr+8)*VV + gc] = v1;
            }
        }
    } else {
        const int b = m0 >> 9;
        const float* gv = gvec + b*HH;
        unsigned short* oh = (unsigned short*)g_A2;
        #pragma unroll
        for (int mi = 0; mi < 2; mi++) {
            const int gr = m0 + wm + mi*16 + lrow;
            #pragma unroll
            for (int ni = 0; ni < 8; ni++) {
                const int gc = n0 + wn + ni*8 + lcol2;   // even
                const float add0 = bias[gc]   + gv[gc];
                const float add1 = bias[gc+1] + gv[gc+1];
                #pragma unroll
                for (int half = 0; half < 2; half++) {
                    const int r = gr + half*8;
                    float v0 = fmaxf(acc[mi][ni][2*half+0] + add0, 0.f);
                    float v1 = fmaxf(acc[mi][ni][2*half+1] + add1, 0.f);
                    __half h0 = __float2half_rn(v0);
                    __half h1 = __float2half_rn(v1);
                    uint32_t pk = (uint32_t)*(unsigned short*)&h0
                                | ((uint32_t)*(unsigned short*)&h1 << 16);
                    *(uint32_t*)&oh[(size_t)r*K2 + gc] = pk;
                }
            }
        }
    }
}

// ---------------- tail ----------------
__global__ void k_tail(const int* __restrict__ tlen, float* __restrict__ out,
                       size_t out_cap)
{
    size_t i = blockIdx.x*blockDim.x + threadIdx.x;
    size_t idx = OUT0 + i;
    if (idx >= out_cap) return;
    if (i < 32) { out[idx] = (float)tlen[i]; return; }
    size_t j = i - 32;
    const size_t S = BB*HH;
    if (j < S)            out[idx] = g_h0[j];
    else if (j < 2*S)     out[idx] = g_h1[j - S];
    else if (j < 3*S)     out[idx] = g_c0[j - 2*S];
    else if (j < 4*S)     out[idx] = g_c1[j - 3*S];
}

// ---------------- launch ----------------
extern "C" void kernel_launch(void* const* d_in, const int* in_sizes, int n_in,
                              void* d_out, int out_size)
{
    const float*      enc    = (const float*)d_in[0];
    const int*        tgt32  = (const int*)d_in[1];
    const int*        tlen   = (const int*)d_in[2];
    const float*      is1    = (const float*)d_in[3];
    const float*      is2    = (const float*)d_in[4];
    const float*      wih0   = (const float*)d_in[5];
    const float*      whh0   = (const float*)d_in[6];
    const float*      bih0   = (const float*)d_in[7];
    const float*      bhh0   = (const float*)d_in[8];
    const float*      wih1   = (const float*)d_in[9];
    const float*      whh1   = (const float*)d_in[10];
    const float*      bih1   = (const float*)d_in[11];
    const float*      bhh1   = (const float*)d_in[12];
    const float*      embed  = (const float*)d_in[13];
    const float*      wenc   = (const float*)d_in[14];
    const float*      benc   = (const float*)d_in[15];
    const float*      wpred  = (const float*)d_in[16];
    const float*      bpred  = (const float*)d_in[17];
    const float*      wout   = (const float*)d_in[18];
    const float*      bout   = (const float*)d_in[19];
    float*            out    = (float*)d_out;

    float *x, *h0, *c0, *h1, *c1, *gj, *part;
    cudaGetSymbolAddress((void**)&x,    g_x);
    cudaGetSymbolAddress((void**)&h0,   g_h0);
    cudaGetSymbolAddress((void**)&c0,   g_c0);
    cudaGetSymbolAddress((void**)&h1,   g_h1);
    cudaGetSymbolAddress((void**)&c1,   g_c1);
    cudaGetSymbolAddress((void**)&gj,   g_g);
    cudaGetSymbolAddress((void**)&part, g_part);

    __half *a1, *b1, *a2, *b2;
    cudaGetSymbolAddress((void**)&a1, g_A1);
    cudaGetSymbolAddress((void**)&b1, g_B1);
    cudaGetSymbolAddress((void**)&a2, g_A2);
    cudaGetSymbolAddress((void**)&b2, g_B2);

    cudaFuncSetAttribute(k_hmma<K1, 0>, cudaFuncAttributeMaxDynamicSharedMemorySize, SMEM_HM);
    cudaFuncSetAttribute(k_hmma<K2, 1>, cudaFuncAttributeMaxDynamicSharedMemorySize, SMEM_HM);

    // decoder (K-split, pipelined k_part2)
    k_embed<<<(BB*HH + 255)/256, 256>>>(tgt32, embed);
    k_part2<<<dim3(H4/32, SPL), 256>>>(x,  is1,          wih0, whh0, part, H4, HH);
    k_redcell<<<(BB*HH + 255)/256, 256>>>(part, is2,          bih0, bhh0, h0, c0);
    k_part2<<<dim3(H4/32, SPL), 256>>>(h0, is1 + BB*HH,  wih1, whh1, part, H4, HH);
    k_redcell<<<(BB*HH + 255)/256, 256>>>(part, is2 + BB*HH,  bih1, bhh1, h1, c1);
    k_part2<<<dim3(HH/32, SPL), 256>>>(h1, nullptr, wpred, nullptr, part, HH, HH);
    k_redpred<<<(BB*HH + 255)/256, 256>>>(part, bpred, gj);

    // staging (encT + weight conversions, one kernel)
    k_stage<<<NB_ENC + NB_WENC + NB_WOUT, 256>>>(enc, wenc, wout);

    // joint network (mma.sync fp16, 3-stage pipeline)
    k_hmma<K1, 0><<<dim3(HH/128, MM/128), 256, SMEM_HM>>>(a1, b1, benc, gj, nullptr);
    k_hmma<K2, 1><<<dim3(VV/128, MM/128), 256, SMEM_HM>>>(a2, b2, bout, nullptr, out);

    // extra tuple outputs
    size_t cap = (size_t)out_size;
    if (cap > OUT0) {
        size_t tail_n = cap - OUT0;
        k_tail<<<(int)((tail_n + 255)/256), 256>>>(tlen, out, cap);
    }
}